// round 1
// baseline (speedup 1.0000x reference)
#include <cuda_runtime.h>
#include <math.h>

#define BB   64
#define TT   512
#define HID  1024
#define ENCD 1024
#define EMB  512
#define VSZ  32000
#define ROWS (BB*TT)          // 32768
#define PRED_OFF (BB*VSZ)     // 2048000
#define HC_SZ (BB*HID)        // 65536

// ---------------- scratch (device globals; no allocation allowed) ----------
__device__ float g_hp[BB*HID];        // h-projection + bias   [b][h]
__device__ float g_spart[ROWS*8];     // partial score sums    [row][ntile]
__device__ float g_wt[BB*TT];         // softmax weights
__device__ float g_ctx[BB*ENCD];      // attention context
__device__ float g_e[BB*EMB];         // embedded token
__device__ float g_gates[BB*4*HID];   // LSTM pre-activations
__device__ float g_hnew[BB*HID];      // new hidden (also written to d_out)

// ---------------- K_emb: e[b,:] = emb_table[tok[b],:] ----------------------
__global__ void k_emb(const int* __restrict__ tok, const float* __restrict__ emb)
{
    int b = blockIdx.x;
    int t = tok[b];
    float4 v = *(const float4*)(emb + (size_t)t * EMB + threadIdx.x * 4);
    *(float4*)(g_e + b * EMB + threadIdx.x * 4) = v;
}

// ---------------- K_hp: hp[b,h] = attn_b[h] + sum_k h0[b,k]*attn_W[h,k] ----
// warp-per-output, lanes stride K with float4 loads (coalesced on attn_W rows)
__global__ void k_hp(const float* __restrict__ attnW,
                     const float* __restrict__ attnB,
                     const float* __restrict__ h0)
{
    int warp = (blockIdx.x * blockDim.x + threadIdx.x) >> 5;   // 0..65535
    int lane = threadIdx.x & 31;
    int b  = warp >> 10;
    int hc = warp & 1023;
    const float* wr = attnW + (size_t)hc * 2048;   // first 1024 cols = h part
    const float* hr = h0 + b * HID;
    float acc = 0.f;
    #pragma unroll
    for (int k0 = lane * 4; k0 < 1024; k0 += 128) {
        float4 w4 = *(const float4*)(wr + k0);
        float4 h4 = *(const float4*)(hr + k0);
        acc += w4.x*h4.x + w4.y*h4.y + w4.z*h4.z + w4.w*h4.w;
    }
    #pragma unroll
    for (int o = 16; o; o >>= 1) acc += __shfl_down_sync(0xffffffffu, acc, o);
    if (!lane) g_hp[warp] = acc + attnB[hc];
}

// ---------------- K2: fused energy GEMM + tanh + v-dot ---------------------
// C[row,h] = sum_k enc[row,k] * attn_W[h,1024+k]   (row = b*512+t)
// spart[row, nt] = sum_{h in tile} tanh(C + hp[b,h]) * v[h]
// 128x128x16 tile, 8x8 micro-tile, 256 threads.
__global__ __launch_bounds__(256) void k2_energy(const float* __restrict__ enc,
                                                 const float* __restrict__ attnW,
                                                 const float* __restrict__ vW)
{
    __shared__ float As[16][132];
    __shared__ float Bs[16][132];
    __shared__ float red[128][16];

    const int m0  = blockIdx.y * 128;
    const int n0  = blockIdx.x * 128;
    const int tid = threadIdx.x;
    const int tx  = tid & 15, ty = tid >> 4;
    const int lr  = tid >> 2;            // 0..63
    const int lk  = (tid & 3) * 4;       // 0,4,8,12

    float acc[8][8];
    #pragma unroll
    for (int i = 0; i < 8; i++)
        #pragma unroll
        for (int j = 0; j < 8; j++) acc[i][j] = 0.f;

    const float* Ag  = enc  + (size_t)(m0 + lr) * 1024 + lk;
    const float* Ag2 = Ag   + (size_t)64 * 1024;
    const float* Bg  = attnW + (size_t)(n0 + lr) * 2048 + 1024 + lk;
    const float* Bg2 = Bg   + (size_t)64 * 2048;

    for (int k0 = 0; k0 < 1024; k0 += 16) {
        float4 a0 = *(const float4*)(Ag  + k0);
        float4 a1 = *(const float4*)(Ag2 + k0);
        float4 b0 = *(const float4*)(Bg  + k0);
        float4 b1 = *(const float4*)(Bg2 + k0);
        __syncthreads();
        As[lk+0][lr]    = a0.x; As[lk+1][lr]    = a0.y; As[lk+2][lr]    = a0.z; As[lk+3][lr]    = a0.w;
        As[lk+0][lr+64] = a1.x; As[lk+1][lr+64] = a1.y; As[lk+2][lr+64] = a1.z; As[lk+3][lr+64] = a1.w;
        Bs[lk+0][lr]    = b0.x; Bs[lk+1][lr]    = b0.y; Bs[lk+2][lr]    = b0.z; Bs[lk+3][lr]    = b0.w;
        Bs[lk+0][lr+64] = b1.x; Bs[lk+1][lr+64] = b1.y; Bs[lk+2][lr+64] = b1.z; Bs[lk+3][lr+64] = b1.w;
        __syncthreads();
        #pragma unroll
        for (int kk = 0; kk < 16; kk++) {
            float4 a04 = *(const float4*)(&As[kk][ty*8]);
            float4 a14 = *(const float4*)(&As[kk][ty*8+4]);
            float4 b04 = *(const float4*)(&Bs[kk][tx*8]);
            float4 b14 = *(const float4*)(&Bs[kk][tx*8+4]);
            float av[8] = {a04.x,a04.y,a04.z,a04.w,a14.x,a14.y,a14.z,a14.w};
            float bv[8] = {b04.x,b04.y,b04.z,b04.w,b14.x,b14.y,b14.z,b14.w};
            #pragma unroll
            for (int i = 0; i < 8; i++)
                #pragma unroll
                for (int j = 0; j < 8; j++) acc[i][j] += av[i]*bv[j];
        }
    }

    // epilogue: tanh + v-weighted reduction over the h (column) dimension
    const int bb = m0 >> 9;                 // one b per 128-row tile (512/128=4)
    float hpv[8], vv[8];
    #pragma unroll
    for (int j = 0; j < 8; j++) {
        int h  = n0 + tx*8 + j;
        hpv[j] = g_hp[bb*1024 + h];
        vv[j]  = vW[h];
    }
    #pragma unroll
    for (int i = 0; i < 8; i++) {
        float s = 0.f;
        #pragma unroll
        for (int j = 0; j < 8; j++) s += tanhf(acc[i][j] + hpv[j]) * vv[j];
        red[ty*8 + i][tx] = s;
    }
    __syncthreads();
    if (tid < 128) {
        float s = 0.f;
        #pragma unroll
        for (int j = 0; j < 16; j++) s += red[tid][j];
        g_spart[(size_t)(m0 + tid) * 8 + blockIdx.x] = s;
    }
}

// ---------------- K3: reduce partials + softmax over T --------------------
__global__ void k3_softmax()
{
    int b = blockIdx.x, t = threadIdx.x;      // 512 threads
    const float* sp = g_spart + (size_t)(b*TT + t) * 8;
    float s = 0.f;
    #pragma unroll
    for (int j = 0; j < 8; j++) s += sp[j];

    __shared__ float sh[512];
    sh[t] = s; __syncthreads();
    for (int off = 256; off > 0; off >>= 1) {
        if (t < off) sh[t] = fmaxf(sh[t], sh[t + off]);
        __syncthreads();
    }
    float mx = sh[0]; __syncthreads();
    float ev = expf(s - mx);
    sh[t] = ev; __syncthreads();
    for (int off = 256; off > 0; off >>= 1) {
        if (t < off) sh[t] += sh[t + off];
        __syncthreads();
    }
    g_wt[b*TT + t] = ev / sh[0];
}

// ---------------- K4: ctx[b,e] = sum_t w[b,t] * enc[b,t,e] ----------------
__global__ void k4_ctx(const float* __restrict__ enc)
{
    int b = blockIdx.x, tid = threadIdx.x;   // 256 threads
    __shared__ float ws[512];
    ws[tid]       = g_wt[b*TT + tid];
    ws[tid + 256] = g_wt[b*TT + 256 + tid];
    __syncthreads();
    float a0=0.f, a1=0.f, a2=0.f, a3=0.f;
    const float* eb = enc + (size_t)b * TT * ENCD;
    #pragma unroll 4
    for (int t = 0; t < TT; t++) {
        float w = ws[t];
        const float* r = eb + (size_t)t * ENCD;
        a0 += w * r[tid];
        a1 += w * r[tid + 256];
        a2 += w * r[tid + 512];
        a3 += w * r[tid + 768];
    }
    g_ctx[b*ENCD + tid]       = a0;
    g_ctx[b*ENCD + tid + 256] = a1;
    g_ctx[b*ENCD + tid + 512] = a2;
    g_ctx[b*ENCD + tid + 768] = a3;
}

// ---------------- K5: LSTM gate pre-activations (warp-per-output) ---------
__global__ void k5_gates(const float* __restrict__ Wih, const float* __restrict__ Whh,
                         const float* __restrict__ bih, const float* __restrict__ bhh,
                         const float* __restrict__ h0)
{
    int warp = (blockIdx.x * blockDim.x + threadIdx.x) >> 5;   // 0..262143
    int lane = threadIdx.x & 31;
    int b = warp >> 12, j = warp & 4095;
    const float* wi = Wih + (size_t)j * 1536;
    float acc = 0.f;
    #pragma unroll
    for (int k0 = lane*4; k0 < 512; k0 += 128) {               // e part
        float4 w4 = *(const float4*)(wi + k0);
        float4 x4 = *(const float4*)(g_e + b*EMB + k0);
        acc += w4.x*x4.x + w4.y*x4.y + w4.z*x4.z + w4.w*x4.w;
    }
    #pragma unroll
    for (int k0 = lane*4; k0 < 1024; k0 += 128) {              // ctx part
        float4 w4 = *(const float4*)(wi + 512 + k0);
        float4 x4 = *(const float4*)(g_ctx + b*ENCD + k0);
        acc += w4.x*x4.x + w4.y*x4.y + w4.z*x4.z + w4.w*x4.w;
    }
    const float* wh = Whh + (size_t)j * 1024;
    #pragma unroll
    for (int k0 = lane*4; k0 < 1024; k0 += 128) {              // h part
        float4 w4 = *(const float4*)(wh + k0);
        float4 x4 = *(const float4*)(h0 + b*HID + k0);
        acc += w4.x*x4.x + w4.y*x4.y + w4.z*x4.z + w4.w*x4.w;
    }
    #pragma unroll
    for (int o = 16; o; o >>= 1) acc += __shfl_down_sync(0xffffffffu, acc, o);
    if (!lane) g_gates[warp] = acc + bih[j] + bhh[j];
}

// ---------------- K6: LSTM elementwise + write h/c outputs ----------------
__device__ __forceinline__ float sigf(float x) { return 1.f / (1.f + expf(-x)); }

__global__ void k6_lstm(const float* __restrict__ c0, float* __restrict__ out)
{
    int idx = blockIdx.x * 256 + threadIdx.x;    // 0..65535
    int b = idx >> 10, u = idx & 1023;
    const float* gb = g_gates + b * 4096;
    float gi = sigf(gb[u]);
    float gf = sigf(gb[1024 + u]);
    float gg = tanhf(gb[2048 + u]);
    float go = sigf(gb[3072 + u]);
    float cn = gf * c0[idx] + gi * gg;
    float hn = go * tanhf(cn);
    g_hnew[idx] = hn;
    out[PRED_OFF + idx]         = hn;
    out[PRED_OFF + HC_SZ + idx] = cn;
}

// ---------------- K7: fc GEMM  pred[b,v] = fc_b[v] + x[b,:]·fc_W[v,:] ------
// x = [h_new | ctx | e], K=2560. 64x128x16 tile, 4x8 micro, 256 threads.
__global__ __launch_bounds__(256) void k7_fc(const float* __restrict__ fcW,
                                             const float* __restrict__ fcb,
                                             float* __restrict__ out)
{
    __shared__ float As[16][68];
    __shared__ float Bs[16][132];
    const int n0  = blockIdx.x * 128;
    const int tid = threadIdx.x;
    const int tx  = tid & 15, ty = tid >> 4;
    const int lr  = tid >> 2;
    const int lk  = (tid & 3) * 4;

    float acc[4][8];
    #pragma unroll
    for (int i = 0; i < 4; i++)
        #pragma unroll
        for (int j = 0; j < 8; j++) acc[i][j] = 0.f;

    const float* Bg  = fcW + (size_t)(n0 + lr) * 2560 + lk;
    const float* Bg2 = Bg  + (size_t)64 * 2560;

    for (int k0 = 0; k0 < 2560; k0 += 16) {
        int k = k0 + lk;
        const float* src; int off;
        if (k < 1024)      { src = g_hnew; off = lr*1024 + k; }
        else if (k < 2048) { src = g_ctx;  off = lr*1024 + (k - 1024); }
        else               { src = g_e;    off = lr*512  + (k - 2048); }
        float4 a0 = *(const float4*)(src + off);
        float4 b0 = *(const float4*)(Bg  + k0);
        float4 b1 = *(const float4*)(Bg2 + k0);
        __syncthreads();
        As[lk+0][lr] = a0.x; As[lk+1][lr] = a0.y; As[lk+2][lr] = a0.z; As[lk+3][lr] = a0.w;
        Bs[lk+0][lr]    = b0.x; Bs[lk+1][lr]    = b0.y; Bs[lk+2][lr]    = b0.z; Bs[lk+3][lr]    = b0.w;
        Bs[lk+0][lr+64] = b1.x; Bs[lk+1][lr+64] = b1.y; Bs[lk+2][lr+64] = b1.z; Bs[lk+3][lr+64] = b1.w;
        __syncthreads();
        #pragma unroll
        for (int kk = 0; kk < 16; kk++) {
            float4 a4  = *(const float4*)(&As[kk][ty*4]);
            float4 b04 = *(const float4*)(&Bs[kk][tx*8]);
            float4 b14 = *(const float4*)(&Bs[kk][tx*8+4]);
            float av[4] = {a4.x, a4.y, a4.z, a4.w};
            float bv[8] = {b04.x,b04.y,b04.z,b04.w,b14.x,b14.y,b14.z,b14.w};
            #pragma unroll
            for (int i = 0; i < 4; i++)
                #pragma unroll
                for (int j = 0; j < 8; j++) acc[i][j] += av[i]*bv[j];
        }
    }
    #pragma unroll
    for (int i = 0; i < 4; i++) {
        int row = ty*4 + i;                       // = b
        float* op = out + (size_t)row * VSZ + n0 + tx*8;
        #pragma unroll
        for (int j = 0; j < 8; j++) op[j] = acc[i][j] + fcb[n0 + tx*8 + j];
    }
}

// ---------------- launch ---------------------------------------------------
extern "C" void kernel_launch(void* const* d_in, const int* in_sizes, int n_in,
                              void* d_out, int out_size)
{
    const int*   tok   = (const int*)  d_in[0];
    const float* h     = (const float*)d_in[1];
    const float* c     = (const float*)d_in[2];
    const float* enc   = (const float*)d_in[3];
    const float* embT  = (const float*)d_in[4];
    const float* attnW = (const float*)d_in[5];
    const float* attnB = (const float*)d_in[6];
    const float* vW    = (const float*)d_in[7];
    const float* Wih   = (const float*)d_in[8];
    const float* Whh   = (const float*)d_in[9];
    const float* bih   = (const float*)d_in[10];
    const float* bhh   = (const float*)d_in[11];
    const float* fcW   = (const float*)d_in[12];
    const float* fcb   = (const float*)d_in[13];
    float* out = (float*)d_out;

    k_emb<<<64, 128>>>(tok, embT);
    k_hp<<<8192, 256>>>(attnW, attnB, h);
    dim3 g2(8, 256);
    k2_energy<<<g2, 256>>>(enc, attnW, vW);
    k3_softmax<<<64, 512>>>();
    k4_ctx<<<64, 256>>>(enc);
    k5_gates<<<32768, 256>>>(Wih, Whh, bih, bhh, h);
    k6_lstm<<<256, 256>>>(c, out);
    k7_fc<<<250, 256>>>(fcW, fcb, out);
}

// round 3
// speedup vs baseline: 2.3090x; 2.3090x over previous
#include <cuda_runtime.h>
#include <cuda_bf16.h>
#include <math.h>
#include <stdint.h>

#define BB   64
#define TT   512
#define HID  1024
#define ENCD 1024
#define EMB  512
#define VSZ  32000
#define ROWS (BB*TT)          // 32768
#define PRED_OFF (BB*VSZ)
#define HC_SZ (BB*HID)
#define KX   2560             // K for both gate and fc GEMMs

// ---------------- scratch (device globals) ---------------------------------
__device__ float g_hp[BB*HID];
__device__ float g_spart[ROWS*4];
__device__ float g_wt[BB*TT];
__device__ float g_ctx[BB*ENCD];
__device__ float g_ctxp[8*BB*ENCD];
__device__ float g_e[BB*EMB];
__device__ float g_gates[BB*4*HID];
__device__ float g_hnew[BB*HID];
__device__ __nv_bfloat16 g_We_hi[1024*1024];
__device__ __nv_bfloat16 g_We_lo[1024*1024];
__device__ __nv_bfloat16 g_x5_hi[BB*KX];
__device__ __nv_bfloat16 g_x5_lo[BB*KX];
__device__ __nv_bfloat16 g_x7_hi[BB*KX];
__device__ __nv_bfloat16 g_x7_lo[BB*KX];

// ---------------- helpers ---------------------------------------------------
__device__ __forceinline__ void split_pair(float x0, float x1, uint32_t& hi, uint32_t& lo)
{
    __nv_bfloat16 h0 = __float2bfloat16_rn(x0);
    __nv_bfloat16 h1 = __float2bfloat16_rn(x1);
    __nv_bfloat16 l0 = __float2bfloat16_rn(x0 - __bfloat162float(h0));
    __nv_bfloat16 l1 = __float2bfloat16_rn(x1 - __bfloat162float(h1));
    __nv_bfloat162 hh; hh.x = h0; hh.y = h1;
    __nv_bfloat162 ll; ll.x = l0; ll.y = l1;
    hi = *reinterpret_cast<uint32_t*>(&hh);
    lo = *reinterpret_cast<uint32_t*>(&ll);
}

__device__ __forceinline__ void ldsm4(uint32_t* r, uint32_t addr)
{
    asm volatile("ldmatrix.sync.aligned.m8n8.x4.shared.b16 {%0,%1,%2,%3}, [%4];"
                 : "=r"(r[0]), "=r"(r[1]), "=r"(r[2]), "=r"(r[3]) : "r"(addr));
}

__device__ __forceinline__ void mma16816(float* c, const uint32_t* a, const uint32_t* b)
{
    asm volatile("mma.sync.aligned.m16n8k16.row.col.f32.bf16.bf16.f32 "
                 "{%0,%1,%2,%3}, {%4,%5,%6,%7}, {%8,%9}, {%0,%1,%2,%3};"
                 : "+f"(c[0]), "+f"(c[1]), "+f"(c[2]), "+f"(c[3])
                 : "r"(a[0]), "r"(a[1]), "r"(a[2]), "r"(a[3]), "r"(b[0]), "r"(b[1]));
}

__device__ __forceinline__ float sigf(float x) { return 1.f / (1.f + expf(-x)); }

// ---------------- K_emb -----------------------------------------------------
__global__ void k_emb(const int* __restrict__ tok, const float* __restrict__ emb)
{
    int b = blockIdx.x;
    int t = tok[b];
    float4 v = *(const float4*)(emb + (size_t)t * EMB + threadIdx.x * 4);
    *(float4*)(g_e + b * EMB + threadIdx.x * 4) = v;
}

// ---------------- K_cvtW: attnW enc-part -> bf16 hi/lo ---------------------
__global__ void k_cvtW(const float* __restrict__ attnW)
{
    int h = blockIdx.x;
    int c4 = threadIdx.x * 4;
    float4 v = *(const float4*)(attnW + (size_t)h * 2048 + 1024 + c4);
    uint32_t h0, l0, h1, l1;
    split_pair(v.x, v.y, h0, l0);
    split_pair(v.z, v.w, h1, l1);
    uint32_t* dh = (uint32_t*)(g_We_hi + (size_t)h * 1024 + c4);
    uint32_t* dl = (uint32_t*)(g_We_lo + (size_t)h * 1024 + c4);
    dh[0] = h0; dh[1] = h1;
    dl[0] = l0; dl[1] = l1;
}

// ---------------- K_hp: h-projection + bias (fp32, tiny) -------------------
__global__ void k_hp(const float* __restrict__ attnW, const float* __restrict__ attnB,
                     const float* __restrict__ h0)
{
    int warp = (blockIdx.x * blockDim.x + threadIdx.x) >> 5;
    int lane = threadIdx.x & 31;
    int b = warp >> 10, hc = warp & 1023;
    const float* wr = attnW + (size_t)hc * 2048;
    const float* hr = h0 + b * HID;
    float acc = 0.f;
    #pragma unroll
    for (int k0 = lane * 4; k0 < 1024; k0 += 128) {
        float4 w4 = *(const float4*)(wr + k0);
        float4 h4 = *(const float4*)(hr + k0);
        acc += w4.x*h4.x + w4.y*h4.y + w4.z*h4.z + w4.w*h4.w;
    }
    #pragma unroll
    for (int o = 16; o; o >>= 1) acc += __shfl_down_sync(0xffffffffu, acc, o);
    if (!lane) g_hp[warp] = acc + attnB[hc];
}

// ---------------- K2: energy GEMM on tensor cores (bf16 3-split) ------------
__global__ __launch_bounds__(512, 1) void k2_energy_mma(const float* __restrict__ enc,
                                                        const float* __restrict__ vW,
                                                        const __nv_bfloat16* __restrict__ Whi,
                                                        const __nv_bfloat16* __restrict__ Wlo,
                                                        const float* __restrict__ hp,
                                                        float* __restrict__ spart)
{
    extern __shared__ __nv_bfloat16 ds[];
    const int tid  = threadIdx.x;
    const int lane = tid & 31;
    const int warp = tid >> 5;
    const int mw = warp >> 2, nw = warp & 3;
    const int m0 = blockIdx.y * 128;
    const int n0 = blockIdx.x * 256;

    const int arow = tid >> 2, acg = (tid & 3) * 8;
    const int brow = tid >> 1, bcg = (tid & 1) * 16;

    const float* aSrc = enc + (size_t)(m0 + arow) * 1024 + acg;
    const __nv_bfloat16* bhSrc = Whi + (size_t)(n0 + brow) * 1024 + bcg;
    const __nv_bfloat16* blSrc = Wlo + (size_t)(n0 + brow) * 1024 + bcg;

    uint32_t smemU = (uint32_t)__cvta_generic_to_shared(ds);

    float acc[2][8][4];
    #pragma unroll
    for (int t = 0; t < 2; t++)
        #pragma unroll
        for (int n = 0; n < 8; n++)
            #pragma unroll
            for (int j = 0; j < 4; j++) acc[t][n][j] = 0.f;

    const int aoff = (mw*32 + (lane & 15)) * 40 + ((lane >> 4) << 3);
    const int boff = (nw*64 + (lane & 7) + ((lane >> 4) << 3)) * 40 + (((lane >> 3) & 1) << 3);

    float4 aPf0, aPf1;
    uint4  bPfh0, bPfh1, bPfl0, bPfl1;

    auto loadPf = [&](int k0) {
        aPf0 = *(const float4*)(aSrc + k0);
        aPf1 = *(const float4*)(aSrc + k0 + 4);
        bPfh0 = *(const uint4*)(bhSrc + k0);
        bPfh1 = *(const uint4*)(bhSrc + k0 + 8);
        bPfl0 = *(const uint4*)(blSrc + k0);
        bPfl1 = *(const uint4*)(blSrc + k0 + 8);
    };
    auto stageStore = [&](int nb) {
        __nv_bfloat16* sAhi = ds + nb * 30720;
        __nv_bfloat16* sAlo = sAhi + 5120;
        __nv_bfloat16* sBhi = sAhi + 10240;
        __nv_bfloat16* sBlo = sAhi + 20480;
        float av[8] = {aPf0.x, aPf0.y, aPf0.z, aPf0.w, aPf1.x, aPf1.y, aPf1.z, aPf1.w};
        uint32_t* dh = (uint32_t*)(sAhi + arow*40 + acg);
        uint32_t* dl = (uint32_t*)(sAlo + arow*40 + acg);
        #pragma unroll
        for (int i = 0; i < 4; i++) {
            uint32_t hi, lo;
            split_pair(av[2*i], av[2*i+1], hi, lo);
            dh[i] = hi; dl[i] = lo;
        }
        uint4* dbh = (uint4*)(sBhi + brow*40 + bcg);
        uint4* dbl = (uint4*)(sBlo + brow*40 + bcg);
        dbh[0] = bPfh0; dbh[1] = bPfh1;
        dbl[0] = bPfl0; dbl[1] = bPfl1;
    };
    auto compute = [&](int cb) {
        uint32_t baseAhi = smemU + cb * 61440;
        uint32_t baseAlo = baseAhi + 10240;
        uint32_t baseBhi = baseAhi + 20480;
        uint32_t baseBlo = baseAhi + 40960;
        #pragma unroll
        for (int ks = 0; ks < 32; ks += 16) {
            uint32_t ah[2][4], al[2][4];
            #pragma unroll
            for (int t = 0; t < 2; t++) {
                ldsm4(ah[t], baseAhi + (uint32_t)(aoff + t*640 + ks) * 2);
                ldsm4(al[t], baseAlo + (uint32_t)(aoff + t*640 + ks) * 2);
            }
            #pragma unroll
            for (int p = 0; p < 4; p++) {
                uint32_t bh[4], bl[4];
                ldsm4(bh, baseBhi + (uint32_t)(boff + p*640 + ks) * 2);
                ldsm4(bl, baseBlo + (uint32_t)(boff + p*640 + ks) * 2);
                #pragma unroll
                for (int t = 0; t < 2; t++) {
                    mma16816(acc[t][2*p],   ah[t], bh);
                    mma16816(acc[t][2*p],   ah[t], bl);
                    mma16816(acc[t][2*p],   al[t], bh);
                    mma16816(acc[t][2*p+1], ah[t], bh + 2);
                    mma16816(acc[t][2*p+1], ah[t], bl + 2);
                    mma16816(acc[t][2*p+1], al[t], bh + 2);
                }
            }
        }
    };

    loadPf(0);
    stageStore(0);
    __syncthreads();
    int cur = 0;
    for (int kt = 0; kt < 32; kt++) {
        if (kt + 1 < 32) loadPf((kt + 1) * 32);
        compute(cur);
        if (kt + 1 < 32) stageStore(cur ^ 1);
        __syncthreads();
        cur ^= 1;
    }

    // epilogue: tanh + v-weighted N-reduction
    const int bb = blockIdx.y >> 2;
    const int g = lane >> 2, tig = lane & 3;
    float* red = (float*)ds;
    #pragma unroll
    for (int t = 0; t < 2; t++) {
        float s0 = 0.f, s1 = 0.f;
        #pragma unroll
        for (int nt = 0; nt < 8; nt++) {
            int col = n0 + nw*64 + nt*8 + tig*2;
            float hp0 = hp[bb*1024 + col], hp1 = hp[bb*1024 + col + 1];
            float v0 = vW[col], v1 = vW[col + 1];
            s0 += tanhf(acc[t][nt][0] + hp0) * v0 + tanhf(acc[t][nt][1] + hp1) * v1;
            s1 += tanhf(acc[t][nt][2] + hp0) * v0 + tanhf(acc[t][nt][3] + hp1) * v1;
        }
        s0 += __shfl_xor_sync(0xffffffffu, s0, 1);
        s0 += __shfl_xor_sync(0xffffffffu, s0, 2);
        s1 += __shfl_xor_sync(0xffffffffu, s1, 1);
        s1 += __shfl_xor_sync(0xffffffffu, s1, 2);
        if (tig == 0) {
            red[(mw*32 + t*16 + g) * 4 + nw]     = s0;
            red[(mw*32 + t*16 + g + 8) * 4 + nw] = s1;
        }
    }
    __syncthreads();
    if (tid < 128) {
        float s = red[tid*4] + red[tid*4+1] + red[tid*4+2] + red[tid*4+3];
        spart[(size_t)(m0 + tid) * 4 + blockIdx.x] = s;
    }
}

// ---------------- K3: softmax ----------------------------------------------
__global__ void k3_softmax()
{
    int b = blockIdx.x, t = threadIdx.x;
    const float* sp = g_spart + (size_t)(b*TT + t) * 4;
    float s = sp[0] + sp[1] + sp[2] + sp[3];
    __shared__ float sh[512];
    sh[t] = s; __syncthreads();
    for (int off = 256; off > 0; off >>= 1) {
        if (t < off) sh[t] = fmaxf(sh[t], sh[t + off]);
        __syncthreads();
    }
    float mx = sh[0]; __syncthreads();
    float ev = expf(s - mx);
    sh[t] = ev; __syncthreads();
    for (int off = 256; off > 0; off >>= 1) {
        if (t < off) sh[t] += sh[t + off];
        __syncthreads();
    }
    g_wt[b*TT + t] = ev / sh[0];
}

// ---------------- K4: ctx partials + reduce ---------------------------------
__global__ void k4_ctx(const float* __restrict__ enc)
{
    int b = blockIdx.x, ch = blockIdx.y, tid = threadIdx.x;
    __shared__ float ws[64];
    if (tid < 64) ws[tid] = g_wt[b*TT + ch*64 + tid];
    __syncthreads();
    const float* eb = enc + (size_t)b * TT * ENCD + (size_t)ch * 64 * ENCD;
    float a0=0.f, a1=0.f, a2=0.f, a3=0.f;
    #pragma unroll 4
    for (int t = 0; t < 64; t++) {
        float w = ws[t];
        const float* r = eb + (size_t)t * ENCD;
        a0 += w * r[tid];
        a1 += w * r[tid + 256];
        a2 += w * r[tid + 512];
        a3 += w * r[tid + 768];
    }
    float* dst = g_ctxp + ((size_t)ch * BB + b) * ENCD;
    dst[tid] = a0; dst[tid+256] = a1; dst[tid+512] = a2; dst[tid+768] = a3;
}

__global__ void k4_reduce()
{
    int b = blockIdx.x, tid = threadIdx.x;
    #pragma unroll
    for (int j = 0; j < 4; j++) {
        int col = tid + j * 256;
        float s = 0.f;
        #pragma unroll
        for (int ch = 0; ch < 8; ch++) s += g_ctxp[((size_t)ch * BB + b) * ENCD + col];
        g_ctx[b*ENCD + col] = s;
    }
}

// ---------------- cvt x vectors to bf16 hi/lo -------------------------------
__global__ void k_cvt_x5(const float* __restrict__ h0)   // [e | ctx | h0]
{
    int b = blockIdx.x, cg = threadIdx.x * 4;
    const float* src;
    if (cg < 512)       src = g_e   + b*EMB  + cg;
    else if (cg < 1536) src = g_ctx + b*ENCD + (cg - 512);
    else                src = h0    + b*HID  + (cg - 1536);
    float4 v = *(const float4*)src;
    uint32_t h0p, l0p, h1p, l1p;
    split_pair(v.x, v.y, h0p, l0p);
    split_pair(v.z, v.w, h1p, l1p);
    uint32_t* dh = (uint32_t*)(g_x5_hi + (size_t)b*KX + cg);
    uint32_t* dl = (uint32_t*)(g_x5_lo + (size_t)b*KX + cg);
    dh[0] = h0p; dh[1] = h1p; dl[0] = l0p; dl[1] = l1p;
}

__global__ void k_cvt_x7()   // [hnew | ctx | e]
{
    int b = blockIdx.x, cg = threadIdx.x * 4;
    const float* src;
    if (cg < 1024)      src = g_hnew + b*HID  + cg;
    else if (cg < 2048) src = g_ctx  + b*ENCD + (cg - 1024);
    else                src = g_e    + b*EMB  + (cg - 2048);
    float4 v = *(const float4*)src;
    uint32_t h0p, l0p, h1p, l1p;
    split_pair(v.x, v.y, h0p, l0p);
    split_pair(v.z, v.w, h1p, l1p);
    uint32_t* dh = (uint32_t*)(g_x7_hi + (size_t)b*KX + cg);
    uint32_t* dl = (uint32_t*)(g_x7_lo + (size_t)b*KX + cg);
    dh[0] = h0p; dh[1] = h1p; dl[0] = l0p; dl[1] = l1p;
}

// ---------------- GEMM64: out[64, N] = x[64,2560] @ W^T + bias --------------
__global__ __launch_bounds__(256, 1) void gemm64(
    const __nv_bfloat16* __restrict__ xhi, const __nv_bfloat16* __restrict__ xlo,
    const float* __restrict__ W1, int ld1, int K1,
    const float* __restrict__ W2, int ld2,
    const float* __restrict__ b1, const float* __restrict__ b2,
    float* __restrict__ out, int ldout)
{
    extern __shared__ __nv_bfloat16 ds[];
    const int tid  = threadIdx.x;
    const int lane = tid & 31;
    const int warp = tid >> 5;
    const int mw = warp >> 2, nw = warp & 3;
    const int n0 = blockIdx.x * 128;

    const int xrow = tid >> 2, xcg = (tid & 3) * 8;
    const int wrow = tid >> 1, wcg = (tid & 1) * 16;

    uint32_t smemU = (uint32_t)__cvta_generic_to_shared(ds);

    float acc[2][4][4];
    #pragma unroll
    for (int t = 0; t < 2; t++)
        #pragma unroll
        for (int n = 0; n < 4; n++)
            #pragma unroll
            for (int j = 0; j < 4; j++) acc[t][n][j] = 0.f;

    const int aoff = (mw*32 + (lane & 15)) * 40 + ((lane >> 4) << 3);
    const int boff = (nw*32 + (lane & 7) + ((lane >> 4) << 3)) * 40 + (((lane >> 3) & 1) << 3);

    uint4 xPh, xPl;
    float4 wPf[4];

    auto loadPf = [&](int k0) {
        xPh = *(const uint4*)(xhi + (size_t)xrow * KX + k0 + xcg);
        xPl = *(const uint4*)(xlo + (size_t)xrow * KX + k0 + xcg);
        const float* wp;
        if (k0 < K1) wp = W1 + (size_t)(n0 + wrow) * ld1 + k0 + wcg;
        else         wp = W2 + (size_t)(n0 + wrow) * ld2 + (k0 - K1) + wcg;
        #pragma unroll
        for (int i = 0; i < 4; i++) wPf[i] = ((const float4*)wp)[i];
    };
    auto stageStore = [&](int nb) {
        __nv_bfloat16* sXhi = ds + nb * 15360;
        __nv_bfloat16* sXlo = sXhi + 2560;
        __nv_bfloat16* sWhi = sXhi + 5120;
        __nv_bfloat16* sWlo = sXhi + 10240;
        *(uint4*)(sXhi + xrow*40 + xcg) = xPh;
        *(uint4*)(sXlo + xrow*40 + xcg) = xPl;
        uint32_t* dh = (uint32_t*)(sWhi + wrow*40 + wcg);
        uint32_t* dl = (uint32_t*)(sWlo + wrow*40 + wcg);
        #pragma unroll
        for (int i = 0; i < 4; i++) {
            uint32_t hi0, lo0, hi1, lo1;
            split_pair(wPf[i].x, wPf[i].y, hi0, lo0);
            split_pair(wPf[i].z, wPf[i].w, hi1, lo1);
            dh[2*i] = hi0; dh[2*i+1] = hi1;
            dl[2*i] = lo0; dl[2*i+1] = lo1;
        }
    };
    auto compute = [&](int cb) {
        uint32_t baseXhi = smemU + cb * 30720;
        uint32_t baseXlo = baseXhi + 5120;
        uint32_t baseWhi = baseXhi + 10240;
        uint32_t baseWlo = baseXhi + 20480;
        #pragma unroll
        for (int ks = 0; ks < 32; ks += 16) {
            uint32_t ah[2][4], al[2][4];
            #pragma unroll
            for (int t = 0; t < 2; t++) {
                ldsm4(ah[t], baseXhi + (uint32_t)(aoff + t*640 + ks) * 2);
                ldsm4(al[t], baseXlo + (uint32_t)(aoff + t*640 + ks) * 2);
            }
            #pragma unroll
            for (int p = 0; p < 2; p++) {
                uint32_t bh[4], bl[4];
                ldsm4(bh, baseWhi + (uint32_t)(boff + p*640 + ks) * 2);
                ldsm4(bl, baseWlo + (uint32_t)(boff + p*640 + ks) * 2);
                #pragma unroll
                for (int t = 0; t < 2; t++) {
                    mma16816(acc[t][2*p],   ah[t], bh);
                    mma16816(acc[t][2*p],   ah[t], bl);
                    mma16816(acc[t][2*p],   al[t], bh);
                    mma16816(acc[t][2*p+1], ah[t], bh + 2);
                    mma16816(acc[t][2*p+1], ah[t], bl + 2);
                    mma16816(acc[t][2*p+1], al[t], bh + 2);
                }
            }
        }
    };

    loadPf(0);
    stageStore(0);
    __syncthreads();
    int cur = 0;
    const int NKT = KX / 32;   // 80
    for (int kt = 0; kt < NKT; kt++) {
        if (kt + 1 < NKT) loadPf((kt + 1) * 32);
        compute(cur);
        if (kt + 1 < NKT) stageStore(cur ^ 1);
        __syncthreads();
        cur ^= 1;
    }

    const int g = lane >> 2, tig = lane & 3;
    #pragma unroll
    for (int t = 0; t < 2; t++) {
        int row = mw*32 + t*16 + g;
        #pragma unroll
        for (int nt = 0; nt < 4; nt++) {
            int col = n0 + nw*32 + nt*8 + tig*2;
            float bv0 = b1[col]     + (b2 ? b2[col]     : 0.f);
            float bv1 = b1[col + 1] + (b2 ? b2[col + 1] : 0.f);
            out[(size_t)row * ldout + col]           = acc[t][nt][0] + bv0;
            out[(size_t)row * ldout + col + 1]       = acc[t][nt][1] + bv1;
            out[(size_t)(row + 8) * ldout + col]     = acc[t][nt][2] + bv0;
            out[(size_t)(row + 8) * ldout + col + 1] = acc[t][nt][3] + bv1;
        }
    }
}

// ---------------- K6: LSTM elementwise ---------------------------------------
__global__ void k6_lstm(const float* __restrict__ c0, float* __restrict__ out)
{
    int idx = blockIdx.x * 256 + threadIdx.x;
    int b = idx >> 10, u = idx & 1023;
    const float* gb = g_gates + b * 4096;
    float gi = sigf(gb[u]);
    float gf = sigf(gb[1024 + u]);
    float gg = tanhf(gb[2048 + u]);
    float go = sigf(gb[3072 + u]);
    float cn = gf * c0[idx] + gi * gg;
    float hn = go * tanhf(cn);
    g_hnew[idx] = hn;
    out[PRED_OFF + idx]         = hn;
    out[PRED_OFF + HC_SZ + idx] = cn;
}

// ---------------- launch -----------------------------------------------------
extern "C" void kernel_launch(void* const* d_in, const int* in_sizes, int n_in,
                              void* d_out, int out_size)
{
    const int*   tok   = (const int*)  d_in[0];
    const float* h     = (const float*)d_in[1];
    const float* c     = (const float*)d_in[2];
    const float* enc   = (const float*)d_in[3];
    const float* embT  = (const float*)d_in[4];
    const float* attnW = (const float*)d_in[5];
    const float* attnB = (const float*)d_in[6];
    const float* vW    = (const float*)d_in[7];
    const float* Wih   = (const float*)d_in[8];
    const float* Whh   = (const float*)d_in[9];
    const float* bih   = (const float*)d_in[10];
    const float* bhh   = (const float*)d_in[11];
    const float* fcW   = (const float*)d_in[12];
    const float* fcb   = (const float*)d_in[13];
    float* out = (float*)d_out;

    cudaFuncSetAttribute(k2_energy_mma, cudaFuncAttributeMaxDynamicSharedMemorySize, 122880);
    cudaFuncSetAttribute(gemm64,        cudaFuncAttributeMaxDynamicSharedMemorySize, 61440);

    // Resolve ALL device-global scratch through cudaGetSymbolAddress.
    // (GB300 ATS: passing the host shadow symbol silently reads host memory.)
    float *gates_p, *hp_p, *spart_p;
    __nv_bfloat16 *wehi_p, *welo_p, *x5h_p, *x5l_p, *x7h_p, *x7l_p;
    cudaGetSymbolAddress((void**)&gates_p, g_gates);
    cudaGetSymbolAddress((void**)&hp_p,    g_hp);
    cudaGetSymbolAddress((void**)&spart_p, g_spart);
    cudaGetSymbolAddress((void**)&wehi_p,  g_We_hi);
    cudaGetSymbolAddress((void**)&welo_p,  g_We_lo);
    cudaGetSymbolAddress((void**)&x5h_p,   g_x5_hi);
    cudaGetSymbolAddress((void**)&x5l_p,   g_x5_lo);
    cudaGetSymbolAddress((void**)&x7h_p,   g_x7_hi);
    cudaGetSymbolAddress((void**)&x7l_p,   g_x7_lo);

    k_emb<<<64, 128>>>(tok, embT);
    k_cvtW<<<1024, 256>>>(attnW);
    k_hp<<<8192, 256>>>(attnW, attnB, h);

    dim3 g2(4, 256);
    k2_energy_mma<<<g2, 512, 122880>>>(enc, vW, wehi_p, welo_p, hp_p, spart_p);
    k3_softmax<<<64, 512>>>();
    dim3 g4(64, 8);
    k4_ctx<<<g4, 256>>>(enc);
    k4_reduce<<<64, 256>>>();

    k_cvt_x5<<<64, 640>>>(h);
    gemm64<<<32, 256, 61440>>>(x5h_p, x5l_p, Wih, 1536, 1536, Whh, 1024,
                               bih, bhh, gates_p, 4096);
    k6_lstm<<<256, 256>>>(c, out);
    k_cvt_x7<<<64, 640>>>();
    gemm64<<<250, 256, 61440>>>(x7h_p, x7l_p, fcW, 2560, 2560, nullptr, 0,
                                fcb, nullptr, out, VSZ);
}